// round 15
// baseline (speedup 1.0000x reference)
#include <cuda_runtime.h>
#include <math.h>
#include <stdint.h>

#define BB 4
#define SS 2048
#define DD 1024
#define HH 16
#define HDD 64
#define M_TOT (BB*SS)     // 8192
#define GKP 1024
#define BK2 32
#define NCH2 (GKP/BK2)    // 32
#define STR2 36           // f32 per smem row (144B)
#define ATS 68
#define QROWS 64
#define KTILE (64*ATS)

// ---------------------------------------------------------------------------
__device__ float g_q[(size_t)BB*HH*SS*HDD];
__device__ float g_k[(size_t)BB*HH*SS*HDD];       // [bh][s][hd], tf32-rounded
__device__ float g_v[(size_t)BB*HH*SS*HDD];       // [bh][hd][s], tf32-rounded (transposed)
__device__ float g_attn[(size_t)BB*SS*DD];
__device__ float g_wt[(size_t)4*DD*DD];
__device__ float g_at[(size_t)3*M_TOT*GKP];

// ---------------------------------------------------------------------------
__device__ __forceinline__ uint32_t smem_u32(const void* p) {
    return (uint32_t)__cvta_generic_to_shared(p);
}
__device__ __forceinline__ void cp16(uint32_t dst, const void* src) {
    asm volatile("cp.async.cg.shared.global [%0], [%1], 16;" :: "r"(dst), "l"(src));
}
__device__ __forceinline__ void cp_commit() {
    asm volatile("cp.async.commit_group;" ::: "memory");
}
template<int N>
__device__ __forceinline__ void cp_wait() {
    asm volatile("cp.async.wait_group %0;" :: "n"(N) : "memory");
}
__device__ __forceinline__ void ldsm4(uint32_t& r0, uint32_t& r1, uint32_t& r2, uint32_t& r3,
                                      uint32_t addr) {
    asm volatile("ldmatrix.sync.aligned.m8n8.x4.shared.b16 {%0,%1,%2,%3}, [%4];"
                 : "=r"(r0), "=r"(r1), "=r"(r2), "=r"(r3) : "r"(addr));
}
__device__ __forceinline__ uint32_t to_tf32(uint32_t x) {
    uint32_t y;
    asm("cvt.rna.tf32.f32 %0, %1;" : "=r"(y) : "r"(x));
    return y;
}
__device__ __forceinline__ float tf32r(float x) {
    return __uint_as_float(to_tf32(__float_as_uint(x)));
}
__device__ __forceinline__ void mma_tf32(float* c, const uint32_t* a, const uint32_t* b) {
    asm volatile("mma.sync.aligned.m16n8k8.row.col.f32.tf32.tf32.f32 "
                 "{%0,%1,%2,%3}, {%4,%5,%6,%7}, {%8,%9}, {%0,%1,%2,%3};"
                 : "+f"(c[0]), "+f"(c[1]), "+f"(c[2]), "+f"(c[3])
                 : "r"(a[0]), "r"(a[1]), "r"(a[2]), "r"(a[3]), "r"(b[0]), "r"(b[1]));
}

// ---------------------------------------------------------------------------
__global__ void __launch_bounds__(1024) prep_w(const float* __restrict__ W0,
                                               const float* __restrict__ W1,
                                               const float* __restrict__ W2,
                                               const float* __restrict__ W3,
                                               float* __restrict__ WT) {
    __shared__ float t[32][33];
    const float* W = (blockIdx.z == 0) ? W0 : (blockIdx.z == 1) ? W1
                   : (blockIdx.z == 2) ? W2 : W3;
    float* out = WT + (size_t)blockIdx.z * DD * DD;
    int k0 = blockIdx.y * 32, n0 = blockIdx.x * 32;
    t[threadIdx.y][threadIdx.x] = W[(size_t)(k0 + threadIdx.y) * 1024 + n0 + threadIdx.x];
    __syncthreads();
    out[(size_t)(n0 + threadIdx.y) * 1024 + k0 + threadIdx.x] = tf32r(t[threadIdx.x][threadIdx.y]);
}

__global__ void __launch_bounds__(256) prep_a(const float4* __restrict__ A0,
                                              const float4* __restrict__ A1,
                                              const float4* __restrict__ A2,
                                              float4* __restrict__ out) {
    const float4* A = (blockIdx.z == 0) ? A0 : (blockIdx.z == 1) ? A1 : A2;
    int idx = blockIdx.x * 256 + threadIdx.x;
    float4 v = A[idx];
    v.x = tf32r(v.x); v.y = tf32r(v.y); v.z = tf32r(v.z); v.w = tf32r(v.w);
    out[(size_t)blockIdx.z * (M_TOT * GKP / 4) + idx] = v;
}

// ---------------------------------------------------------------------------
// tf32 GEMM v3: CTA 128x128, 4 warps (2m x 2n), warp tile 64x64, BK=32,
// 128 threads, 2 CTAs/SM. Same smem layout/staging; same accumulation order
// per output element as R14 -> bit-identical results.
// ---------------------------------------------------------------------------
template<bool QKV>
__global__ void __launch_bounds__(128, 2) gemm32(const float* __restrict__ Abase,
                                                 const float* __restrict__ Bbase,
                                                 float* __restrict__ Cq,
                                                 float* __restrict__ Ck,
                                                 float* __restrict__ Cv) {
    extern __shared__ float smg[];
    const uint32_t sbase = smem_u32(smg);

    const int z    = QKV ? blockIdx.z : 0;
    const int tid  = threadIdx.x;
    const int lane = tid & 31;
    const int warp = tid >> 5;          // 0..3
    const int wm   = warp & 1;          // 0..1 (64 m)
    const int wn   = warp >> 1;         // 0..1 (64 n)
    const int m0   = blockIdx.y * 128;
    const int n0   = blockIdx.x * 128;

    const float* A = Abase + (QKV ? (size_t)z * M_TOT * GKP : 0);
    const float* B = Bbase + (QKV ? (size_t)z * DD * DD : 0);
    const float* Arow = A + (size_t)m0 * GKP;
    const float* Brow = B + (size_t)n0 * GKP;

    auto load_chunk = [&](int buf, int c) {
        const size_t kof = (size_t)c * BK2;
        const uint32_t dA = sbase + (buf ? 4608u : 0u) * 4u;
        const uint32_t dB = sbase + (buf ? 13824u : 9216u) * 4u;
#pragma unroll
        for (int u = 0; u < 8; u++) {
            int task = tid + u * 128;       // 0..1023
            int row  = task >> 3;
            int seg  = task & 7;
            uint32_t so = (uint32_t)(row * STR2 + seg * 4) * 4;
            cp16(dA + so, Arow + (size_t)row * GKP + kof + seg * 4);
            cp16(dB + so, Brow + (size_t)row * GKP + kof + seg * 4);
        }
        cp_commit();
    };

    float acc[4][8][4];
#pragma unroll
    for (int i = 0; i < 4; i++)
#pragma unroll
        for (int j = 0; j < 8; j++)
#pragma unroll
            for (int r = 0; r < 4; r++) acc[i][j][r] = 0.f;

    load_chunk(0, 0);

    for (int c = 0; c < NCH2; c++) {
        const int buf = c & 1;
        if (c + 1 < NCH2) {
            load_chunk(buf ^ 1, c + 1);
            cp_wait<1>();
        } else {
            cp_wait<0>();
        }
        __syncthreads();

        const uint32_t sA = sbase + (buf ? 4608u : 0u) * 4u;
        const uint32_t sB = sbase + (buf ? 13824u : 9216u) * 4u;
        const uint32_t aBase = sA + (uint32_t)((wm * 64 + (lane & 15)) * STR2) * 4
                             + (lane >> 4) * 16;
        const uint32_t bBase = sB + (uint32_t)((wn * 64 + ((lane >> 4) & 1) * 8 + (lane & 7)) * STR2) * 4
                             + ((lane >> 3) & 1) * 16;
#pragma unroll
        for (int k8 = 0; k8 < 4; k8++) {
            const uint32_t kb = k8 * 32;
            uint32_t a[4][4];
#pragma unroll
            for (int mf = 0; mf < 4; mf++)
                ldsm4(a[mf][0], a[mf][1], a[mf][2], a[mf][3],
                      aBase + (uint32_t)(mf * 16 * STR2) * 4 + kb);
            uint32_t b[8][2];
#pragma unroll
            for (int bb = 0; bb < 4; bb++) {
                uint32_t r0, r1, r2, r3;
                ldsm4(r0, r1, r2, r3, bBase + (uint32_t)(bb * 16 * STR2) * 4 + kb);
                b[bb * 2 + 0][0] = r0; b[bb * 2 + 0][1] = r1;
                b[bb * 2 + 1][0] = r2; b[bb * 2 + 1][1] = r3;
            }
#pragma unroll
            for (int mf = 0; mf < 4; mf++)
#pragma unroll
                for (int nf = 0; nf < 8; nf++)
                    mma_tf32(acc[mf][nf], a[mf], b[nf]);
        }
        __syncthreads();
    }

    const int grp = lane >> 2;
    const int tg  = lane & 3;
#pragma unroll
    for (int mf = 0; mf < 4; mf++) {
#pragma unroll
        for (int nf = 0; nf < 8; nf++) {
            int n = n0 + wn * 64 + nf * 8 + tg * 2;
#pragma unroll
            for (int half = 0; half < 2; half++) {
                int m = m0 + wm * 64 + mf * 16 + grp + half * 8;
                float2 v = make_float2(acc[mf][nf][half * 2], acc[mf][nf][half * 2 + 1]);
                if (!QKV) {
                    *(float2*)&Cq[(size_t)m * DD + n] = v;
                } else {
                    int b_ = m >> 11, s_ = m & 2047;
                    int h_ = n >> 6,  hd = n & 63;
                    if (z == 0) {
                        *(float2*)&Cq[((size_t)(b_ * HH + h_) * SS + s_) * HDD + hd] = v;
                    } else if (z == 1) {
                        v.x = tf32r(v.x); v.y = tf32r(v.y);
                        *(float2*)&Ck[((size_t)(b_ * HH + h_) * SS + s_) * HDD + hd] = v;
                    } else {
                        size_t base = ((size_t)(b_ * HH + h_) * HDD + hd) * SS + s_;
                        Cv[base]      = tf32r(v.x);
                        Cv[base + SS] = tf32r(v.y);
                    }
                }
            }
        }
    }
}

// ---------------------------------------------------------------------------
__device__ __forceinline__ float fast_exp(float x) {
    float t = fmaxf(x * 1.4426950408889634f, -126.0f);
    int   i = __float2int_rn(t);
    float f = t - (float)i;
    float p = 1.3333558146428443e-3f;
    p = fmaf(p, f, 9.6181291076284771e-3f);
    p = fmaf(p, f, 5.5504108664821580e-2f);
    p = fmaf(p, f, 2.4022650695910072e-1f);
    p = fmaf(p, f, 6.9314718055994531e-1f);
    p = fmaf(p, f, 1.0f);
    return p * __int_as_float((i + 127) << 23);
}

// ---------------------------------------------------------------------------
// Flash attention v8 (unchanged from R14): shuffle-built P fragments,
// 3*KTILE smem -> 4 CTAs/SM.
// ---------------------------------------------------------------------------
__global__ void __launch_bounds__(128, 4) attn_mma(const int* __restrict__ valid_lens,
                                                   float* __restrict__ out) {
    extern __shared__ float smf[];
    float* Qh = smf;

    int vl[4];
#pragma unroll
    for (int i = 0; i < 4; i++) vl[i] = valid_lens[i];
    int ord[4] = {0, 1, 2, 3};
#pragma unroll
    for (int i = 0; i < 3; i++)
#pragma unroll
        for (int j = i + 1; j < 4; j++)
            if (vl[ord[j]] > vl[ord[i]]) { int t = ord[i]; ord[i] = ord[j]; ord[j] = t; }

    const int qt = blockIdx.x;
    const int b  = ord[blockIdx.y >> 4];
    const int h  = blockIdx.y & 15;
    const int vlen = vl[b];
    const int bh = b * HH + h;

    const float* q = g_q + (size_t)bh * (SS * HDD);
    const float* k = g_k + (size_t)bh * (SS * HDD);
    const float* v = g_v + (size_t)bh * (HDD * SS);

    const int tid  = threadIdx.x;
    const int lane = tid & 31;
    const int w    = tid >> 5;
    const int grp  = lane >> 2;
    const int tg   = lane & 3;

    const uint32_t sQh = smem_u32(Qh);
    const uint32_t sK  = sQh + (uint32_t)(KTILE) * 4u;
    const uint32_t sV  = sQh + (uint32_t)(2 * KTILE) * 4u;

#pragma unroll
    for (int i = 0; i < 8; i++) {
        int idx = tid + i * 128;
        int row = idx >> 4, c4 = (idx & 15) << 2;
        float4 t = *(const float4*)&q[(size_t)(qt * QROWS + row) * HDD + c4];
        t.x = tf32r(t.x); t.y = tf32r(t.y); t.z = tf32r(t.z); t.w = tf32r(t.w);
        *(float4*)&Qh[row * ATS + c4] = t;
    }

    auto stage_kv = [&](int kt) {
        const int kof = kt * 64;
#pragma unroll
        for (int i = 0; i < 8; i++) {
            int task = tid + i * 128;
            int row = task >> 4, seg = task & 15;
            cp16(sK + (uint32_t)(row * ATS + seg * 4) * 4,
                 k + (size_t)(kof + row) * HDD + seg * 4);
            cp16(sV + (uint32_t)(row * ATS + seg * 4) * 4,
                 v + (size_t)row * SS + kof + seg * 4);
        }
        cp_commit();
    };

    float m_i[2] = {-1e30f, -1e30f}, l_i[2] = {0.f, 0.f};
    float O[8][4];
#pragma unroll
    for (int nf = 0; nf < 8; nf++)
#pragma unroll
        for (int r = 0; r < 4; r++) O[nf][r] = 0.f;

    const uint32_t aOff = (uint32_t)((w * 16 + (lane & 15)) * ATS) * 4 + (lane >> 4) * 16;
    const uint32_t bOff = (uint32_t)((((lane >> 4) & 1) * 8 + (lane & 7)) * ATS) * 4
                        + ((lane >> 3) & 1) * 16;
    const int shfl_s0 = (lane & ~3) | (tg >> 1);
    const int shfl_s1 = shfl_s0 | 2;
    const bool todd = tg & 1;

    const int ntiles = (vlen + 63) >> 6;

    for (int kt = 0; kt < ntiles; kt++) {
        stage_kv(kt);
        cp_wait<0>();
        __syncthreads();

        float sacc[8][4];
#pragma unroll
        for (int nf = 0; nf < 8; nf++)
#pragma unroll
            for (int r = 0; r < 4; r++) sacc[nf][r] = 0.f;

#pragma unroll
        for (int k8 = 0; k8 < 8; k8++) {
            const uint32_t kb = k8 * 32;
            uint32_t qh[4];
            ldsm4(qh[0], qh[1], qh[2], qh[3], sQh + aOff + kb);
#pragma unroll
            for (int bbq = 0; bbq < 4; bbq++) {
                uint32_t kh[4];
                ldsm4(kh[0], kh[1], kh[2], kh[3],
                      sK + bOff + (uint32_t)(bbq * 16 * ATS) * 4 + kb);
                mma_tf32(sacc[bbq*2+0], qh, &kh[0]);
                mma_tf32(sacc[bbq*2+1], qh, &kh[2]);
            }
        }

        const int kbase = kt * 64;
#pragma unroll
        for (int nf = 0; nf < 8; nf++) {
            int cg = kbase + nf * 8 + 2 * tg;
            bool mk0 = cg >= vlen, mk1 = (cg + 1) >= vlen;
#pragma unroll
            for (int hh = 0; hh < 2; hh++) {
                sacc[nf][hh*2+0] = mk0 ? -1e30f : sacc[nf][hh*2+0] * 0.125f;
                sacc[nf][hh*2+1] = mk1 ? -1e30f : sacc[nf][hh*2+1] * 0.125f;
            }
        }

#pragma unroll
        for (int hh = 0; hh < 2; hh++) {
            float mx = -1e30f;
#pragma unroll
            for (int nf = 0; nf < 8; nf++)
                mx = fmaxf(mx, fmaxf(sacc[nf][hh*2], sacc[nf][hh*2+1]));
            mx = fmaxf(mx, __shfl_xor_sync(0xffffffffu, mx, 1));
            mx = fmaxf(mx, __shfl_xor_sync(0xffffffffu, mx, 2));
            float m_new = fmaxf(m_i[hh], mx);
            float scl = fast_exp(m_i[hh] - m_new);
            m_i[hh] = m_new;
            float ps = 0.f;
#pragma unroll
            for (int nf = 0; nf < 8; nf++) {
                float p0 = fast_exp(sacc[nf][hh*2+0] - m_new);
                float p1 = fast_exp(sacc[nf][hh*2+1] - m_new);
                ps += p0 + p1;
                sacc[nf][hh*2+0] = tf32r(p0);
                sacc[nf][hh*2+1] = tf32r(p1);
            }
            ps += __shfl_xor_sync(0xffffffffu, ps, 1);
            ps += __shfl_xor_sync(0xffffffffu, ps, 2);
            l_i[hh] = l_i[hh] * scl + ps;
#pragma unroll
            for (int nf = 0; nf < 8; nf++) {
                O[nf][hh*2+0] *= scl;
                O[nf][hh*2+1] *= scl;
            }
        }

#pragma unroll
        for (int k8 = 0; k8 < 8; k8++) {
            const uint32_t kb = k8 * 32;
            float e0 = sacc[k8][0], e1 = sacc[k8][1];
            float f0 = sacc[k8][2], f1 = sacc[k8][3];
            float e0a = __shfl_sync(0xffffffffu, e0, shfl_s0);
            float e1a = __shfl_sync(0xffffffffu, e1, shfl_s0);
            float f0a = __shfl_sync(0xffffffffu, f0, shfl_s0);
            float f1a = __shfl_sync(0xffffffffu, f1, shfl_s0);
            float e0b = __shfl_sync(0xffffffffu, e0, shfl_s1);
            float e1b = __shfl_sync(0xffffffffu, e1, shfl_s1);
            float f0b = __shfl_sync(0xffffffffu, f0, shfl_s1);
            float f1b = __shfl_sync(0xffffffffu, f1, shfl_s1);
            uint32_t ap[4];
            ap[0] = __float_as_uint(todd ? e1a : e0a);
            ap[1] = __float_as_uint(todd ? f1a : f0a);
            ap[2] = __float_as_uint(todd ? e1b : e0b);
            ap[3] = __float_as_uint(todd ? f1b : f0b);
#pragma unroll
            for (int bbv = 0; bbv < 4; bbv++) {
                uint32_t r0, r1, r2, r3;
                ldsm4(r0, r1, r2, r3, sV + bOff + (uint32_t)(bbv * 16 * ATS) * 4 + kb);
                uint32_t b0[2] = {r0, r1}, b1[2] = {r2, r3};
                mma_tf32(O[bbv*2+0], ap, b0);
                mma_tf32(O[bbv*2+1], ap, b1);
            }
        }
        __syncthreads();
    }

#pragma unroll
    for (int hh = 0; hh < 2; hh++) {
        float inv = 1.f / l_i[hh];
        int srow = qt * QROWS + w * 16 + grp + hh * 8;
#pragma unroll
        for (int nf = 0; nf < 8; nf++) {
            int hd = nf * 8 + 2 * tg;
            float2 val = make_float2(tf32r(O[nf][hh*2+0] * inv), tf32r(O[nf][hh*2+1] * inv));
            *(float2*)&out[((size_t)b * SS + srow) * DD + h * HDD + hd] = val;
        }
    }
}

// ---------------------------------------------------------------------------
extern "C" void kernel_launch(void* const* d_in, const int* in_sizes, int n_in,
                              void* d_out, int out_size) {
    (void)in_sizes; (void)n_in; (void)out_size;
    const float* queries    = (const float*)d_in[0];
    const float* keys       = (const float*)d_in[1];
    const float* values     = (const float*)d_in[2];
    const int*   valid_lens = (const int*)  d_in[3];
    const float* Wq         = (const float*)d_in[4];
    const float* Wk         = (const float*)d_in[5];
    const float* Wv         = (const float*)d_in[6];
    const float* Wo         = (const float*)d_in[7];
    float* out = (float*)d_out;

    float *pq, *pk, *pv, *pa, *pwt, *pat;
    cudaGetSymbolAddress((void**)&pq, g_q);
    cudaGetSymbolAddress((void**)&pk, g_k);
    cudaGetSymbolAddress((void**)&pv, g_v);
    cudaGetSymbolAddress((void**)&pa, g_attn);
    cudaGetSymbolAddress((void**)&pwt, g_wt);
    cudaGetSymbolAddress((void**)&pat, g_at);

    const int gemm_smem = 4 * 128 * STR2 * sizeof(float);     // 73728
    cudaFuncSetAttribute(gemm32<true>,  cudaFuncAttributeMaxDynamicSharedMemorySize, gemm_smem);
    cudaFuncSetAttribute(gemm32<false>, cudaFuncAttributeMaxDynamicSharedMemorySize, gemm_smem);
    const int attn_smem = 3 * KTILE * sizeof(float);          // 52224 -> 4 CTAs/SM
    cudaFuncSetAttribute(attn_mma, cudaFuncAttributeMaxDynamicSharedMemorySize, attn_smem);

    // prep
    dim3 pw_grid(32, 32, 4), pw_blk(32, 32);
    prep_w<<<pw_grid, pw_blk>>>(Wq, Wk, Wv, Wo, pwt);
    dim3 pa_grid(M_TOT * GKP / 4 / 256, 1, 3);
    prep_a<<<pa_grid, 256>>>((const float4*)queries, (const float4*)keys,
                             (const float4*)values, (float4*)pat);

    // fused QKV projections (1536 CTAs, 128 thr, 2 CTAs/SM)
    dim3 gq(DD / 128, M_TOT / 128, 3);
    gemm32<true><<<gq, 128, gemm_smem>>>(pat, pwt, pq, pk, pv);

    // attention
    dim3 agrid(SS / QROWS, BB * HH);
    attn_mma<<<agrid, 128, attn_smem>>>(valid_lens, pa);

    // output projection
    dim3 go(DD / 128, M_TOT / 128, 1);
    gemm32<false><<<go, 128, gemm_smem>>>(pa, pwt + (size_t)3 * DD * DD, out, nullptr, nullptr);
}

// round 16
// speedup vs baseline: 1.0212x; 1.0212x over previous
#include <cuda_runtime.h>
#include <math.h>
#include <stdint.h>

#define BB 4
#define SS 2048
#define DD 1024
#define HH 16
#define HDD 64
#define M_TOT (BB*SS)     // 8192
#define GKP 1024
#define BK2 32
#define NCH2 (GKP/BK2)    // 32
#define STR2 36           // f32 per smem row (144B)
#define ATS 68
#define QROWS 64
#define KTILE (64*ATS)

// ---------------------------------------------------------------------------
__device__ float g_q[(size_t)BB*HH*SS*HDD];
__device__ float g_k[(size_t)BB*HH*SS*HDD];       // [bh][s][hd], tf32-rounded
__device__ float g_v[(size_t)BB*HH*SS*HDD];       // [bh][hd][s], tf32-rounded (transposed)
__device__ float g_attn[(size_t)BB*SS*DD];
__device__ float g_wt[(size_t)4*DD*DD];
__device__ float g_at[(size_t)3*M_TOT*GKP];

// ---------------------------------------------------------------------------
__device__ __forceinline__ uint32_t smem_u32(const void* p) {
    return (uint32_t)__cvta_generic_to_shared(p);
}
__device__ __forceinline__ void cp16(uint32_t dst, const void* src) {
    asm volatile("cp.async.cg.shared.global [%0], [%1], 16;" :: "r"(dst), "l"(src));
}
__device__ __forceinline__ void cp_commit() {
    asm volatile("cp.async.commit_group;" ::: "memory");
}
template<int N>
__device__ __forceinline__ void cp_wait() {
    asm volatile("cp.async.wait_group %0;" :: "n"(N) : "memory");
}
__device__ __forceinline__ void ldsm4(uint32_t& r0, uint32_t& r1, uint32_t& r2, uint32_t& r3,
                                      uint32_t addr) {
    asm volatile("ldmatrix.sync.aligned.m8n8.x4.shared.b16 {%0,%1,%2,%3}, [%4];"
                 : "=r"(r0), "=r"(r1), "=r"(r2), "=r"(r3) : "r"(addr));
}
__device__ __forceinline__ uint32_t to_tf32(uint32_t x) {
    uint32_t y;
    asm("cvt.rna.tf32.f32 %0, %1;" : "=r"(y) : "r"(x));
    return y;
}
__device__ __forceinline__ float tf32r(float x) {
    return __uint_as_float(to_tf32(__float_as_uint(x)));
}
__device__ __forceinline__ void mma_tf32(float* c, const uint32_t* a, const uint32_t* b) {
    asm volatile("mma.sync.aligned.m16n8k8.row.col.f32.tf32.tf32.f32 "
                 "{%0,%1,%2,%3}, {%4,%5,%6,%7}, {%8,%9}, {%0,%1,%2,%3};"
                 : "+f"(c[0]), "+f"(c[1]), "+f"(c[2]), "+f"(c[3])
                 : "r"(a[0]), "r"(a[1]), "r"(a[2]), "r"(a[3]), "r"(b[0]), "r"(b[1]));
}

// ---------------------------------------------------------------------------
__global__ void __launch_bounds__(1024) prep_w(const float* __restrict__ W0,
                                               const float* __restrict__ W1,
                                               const float* __restrict__ W2,
                                               const float* __restrict__ W3,
                                               float* __restrict__ WT) {
    __shared__ float t[32][33];
    const float* W = (blockIdx.z == 0) ? W0 : (blockIdx.z == 1) ? W1
                   : (blockIdx.z == 2) ? W2 : W3;
    float* out = WT + (size_t)blockIdx.z * DD * DD;
    int k0 = blockIdx.y * 32, n0 = blockIdx.x * 32;
    t[threadIdx.y][threadIdx.x] = W[(size_t)(k0 + threadIdx.y) * 1024 + n0 + threadIdx.x];
    __syncthreads();
    out[(size_t)(n0 + threadIdx.y) * 1024 + k0 + threadIdx.x] = tf32r(t[threadIdx.x][threadIdx.y]);
}

__global__ void __launch_bounds__(256) prep_a(const float4* __restrict__ A0,
                                              const float4* __restrict__ A1,
                                              const float4* __restrict__ A2,
                                              float4* __restrict__ out) {
    const float4* A = (blockIdx.z == 0) ? A0 : (blockIdx.z == 1) ? A1 : A2;
    int idx = blockIdx.x * 256 + threadIdx.x;
    float4 v = A[idx];
    v.x = tf32r(v.x); v.y = tf32r(v.y); v.z = tf32r(v.z); v.w = tf32r(v.w);
    out[(size_t)blockIdx.z * (M_TOT * GKP / 4) + idx] = v;
}

// ---------------------------------------------------------------------------
// tf32 GEMM (R14 config, reverted): CTA 128x128, 8 warps (2m x 4n),
// warp tile 64x32, BK=32, 256 threads, 2 CTAs/SM.
// ---------------------------------------------------------------------------
template<bool QKV>
__global__ void __launch_bounds__(256, 2) gemm32(const float* __restrict__ Abase,
                                                 const float* __restrict__ Bbase,
                                                 float* __restrict__ Cq,
                                                 float* __restrict__ Ck,
                                                 float* __restrict__ Cv) {
    extern __shared__ float smg[];
    const uint32_t sbase = smem_u32(smg);

    const int z    = QKV ? blockIdx.z : 0;
    const int tid  = threadIdx.x;
    const int lane = tid & 31;
    const int warp = tid >> 5;
    const int wm   = warp & 1;
    const int wn   = warp >> 1;
    const int m0   = blockIdx.y * 128;
    const int n0   = blockIdx.x * 128;

    const float* A = Abase + (QKV ? (size_t)z * M_TOT * GKP : 0);
    const float* B = Bbase + (QKV ? (size_t)z * DD * DD : 0);
    const float* Arow = A + (size_t)m0 * GKP;
    const float* Brow = B + (size_t)n0 * GKP;

    auto load_chunk = [&](int buf, int c) {
        const size_t kof = (size_t)c * BK2;
        const uint32_t dA = sbase + (buf ? 4608u : 0u) * 4u;
        const uint32_t dB = sbase + (buf ? 13824u : 9216u) * 4u;
#pragma unroll
        for (int u = 0; u < 4; u++) {
            int task = tid + u * 256;
            int row  = task >> 3;
            int seg  = task & 7;
            uint32_t so = (uint32_t)(row * STR2 + seg * 4) * 4;
            cp16(dA + so, Arow + (size_t)row * GKP + kof + seg * 4);
            cp16(dB + so, Brow + (size_t)row * GKP + kof + seg * 4);
        }
        cp_commit();
    };

    float acc[4][4][4];
#pragma unroll
    for (int i = 0; i < 4; i++)
#pragma unroll
        for (int j = 0; j < 4; j++)
#pragma unroll
            for (int r = 0; r < 4; r++) acc[i][j][r] = 0.f;

    load_chunk(0, 0);

    for (int c = 0; c < NCH2; c++) {
        const int buf = c & 1;
        if (c + 1 < NCH2) {
            load_chunk(buf ^ 1, c + 1);
            cp_wait<1>();
        } else {
            cp_wait<0>();
        }
        __syncthreads();

        const uint32_t sA = sbase + (buf ? 4608u : 0u) * 4u;
        const uint32_t sB = sbase + (buf ? 13824u : 9216u) * 4u;
        const uint32_t aBase = sA + (uint32_t)((wm * 64 + (lane & 15)) * STR2) * 4
                             + (lane >> 4) * 16;
        const uint32_t bBase = sB + (uint32_t)((wn * 32 + ((lane >> 4) & 1) * 8 + (lane & 7)) * STR2) * 4
                             + ((lane >> 3) & 1) * 16;
#pragma unroll
        for (int k8 = 0; k8 < 4; k8++) {
            const uint32_t kb = k8 * 32;
            uint32_t a[4][4];
#pragma unroll
            for (int mf = 0; mf < 4; mf++)
                ldsm4(a[mf][0], a[mf][1], a[mf][2], a[mf][3],
                      aBase + (uint32_t)(mf * 16 * STR2) * 4 + kb);
            uint32_t b[4][2];
#pragma unroll
            for (int bb = 0; bb < 2; bb++) {
                uint32_t r0, r1, r2, r3;
                ldsm4(r0, r1, r2, r3, bBase + (uint32_t)(bb * 16 * STR2) * 4 + kb);
                b[bb * 2 + 0][0] = r0; b[bb * 2 + 0][1] = r1;
                b[bb * 2 + 1][0] = r2; b[bb * 2 + 1][1] = r3;
            }
#pragma unroll
            for (int mf = 0; mf < 4; mf++)
#pragma unroll
                for (int nf = 0; nf < 4; nf++)
                    mma_tf32(acc[mf][nf], a[mf], b[nf]);
        }
        __syncthreads();
    }

    const int grp = lane >> 2;
    const int tg  = lane & 3;
#pragma unroll
    for (int mf = 0; mf < 4; mf++) {
#pragma unroll
        for (int nf = 0; nf < 4; nf++) {
            int n = n0 + wn * 32 + nf * 8 + tg * 2;
#pragma unroll
            for (int half = 0; half < 2; half++) {
                int m = m0 + wm * 64 + mf * 16 + grp + half * 8;
                float2 v = make_float2(acc[mf][nf][half * 2], acc[mf][nf][half * 2 + 1]);
                if (!QKV) {
                    *(float2*)&Cq[(size_t)m * DD + n] = v;
                } else {
                    int b_ = m >> 11, s_ = m & 2047;
                    int h_ = n >> 6,  hd = n & 63;
                    if (z == 0) {
                        *(float2*)&Cq[((size_t)(b_ * HH + h_) * SS + s_) * HDD + hd] = v;
                    } else if (z == 1) {
                        v.x = tf32r(v.x); v.y = tf32r(v.y);
                        *(float2*)&Ck[((size_t)(b_ * HH + h_) * SS + s_) * HDD + hd] = v;
                    } else {
                        size_t base = ((size_t)(b_ * HH + h_) * HDD + hd) * SS + s_;
                        Cv[base]      = tf32r(v.x);
                        Cv[base + SS] = tf32r(v.y);
                    }
                }
            }
        }
    }
}

// ---------------------------------------------------------------------------
__device__ __forceinline__ float fast_exp(float x) {
    float t = x * 1.4426950408889634f;
    int   i = __float2int_rn(t);
    float f = t - (float)i;
    float p = 1.3333558146428443e-3f;
    p = fmaf(p, f, 9.6181291076284771e-3f);
    p = fmaf(p, f, 5.5504108664821580e-2f);
    p = fmaf(p, f, 2.4022650695910072e-1f);
    p = fmaf(p, f, 6.9314718055994531e-1f);
    p = fmaf(p, f, 1.0f);
    return p * __int_as_float((i + 127) << 23);
}

// ---------------------------------------------------------------------------
// Flash attention v9: NO online max (scores bounded, softmax shift-invariant,
// masked lanes write p=0); shuffle-built P fragments; 3*KTILE smem -> 4 CTAs/SM.
// Per tile: S-mma -> exp -> PV-mma. Row sums deferred to epilogue.
// ---------------------------------------------------------------------------
__global__ void __launch_bounds__(128, 4) attn_mma(const int* __restrict__ valid_lens,
                                                   float* __restrict__ out) {
    extern __shared__ float smf[];
    float* Qh = smf;

    int vl[4];
#pragma unroll
    for (int i = 0; i < 4; i++) vl[i] = valid_lens[i];
    int ord[4] = {0, 1, 2, 3};
#pragma unroll
    for (int i = 0; i < 3; i++)
#pragma unroll
        for (int j = i + 1; j < 4; j++)
            if (vl[ord[j]] > vl[ord[i]]) { int t = ord[i]; ord[i] = ord[j]; ord[j] = t; }

    const int qt = blockIdx.x;
    const int b  = ord[blockIdx.y >> 4];
    const int h  = blockIdx.y & 15;
    const int vlen = vl[b];
    const int bh = b * HH + h;

    const float* q = g_q + (size_t)bh * (SS * HDD);
    const float* k = g_k + (size_t)bh * (SS * HDD);
    const float* v = g_v + (size_t)bh * (HDD * SS);

    const int tid  = threadIdx.x;
    const int lane = tid & 31;
    const int w    = tid >> 5;
    const int grp  = lane >> 2;
    const int tg   = lane & 3;

    const uint32_t sQh = smem_u32(Qh);
    const uint32_t sK  = sQh + (uint32_t)(KTILE) * 4u;
    const uint32_t sV  = sQh + (uint32_t)(2 * KTILE) * 4u;

#pragma unroll
    for (int i = 0; i < 8; i++) {
        int idx = tid + i * 128;
        int row = idx >> 4, c4 = (idx & 15) << 2;
        float4 t = *(const float4*)&q[(size_t)(qt * QROWS + row) * HDD + c4];
        t.x = tf32r(t.x); t.y = tf32r(t.y); t.z = tf32r(t.z); t.w = tf32r(t.w);
        *(float4*)&Qh[row * ATS + c4] = t;
    }

    auto stage_kv = [&](int kt) {
        const int kof = kt * 64;
#pragma unroll
        for (int i = 0; i < 8; i++) {
            int task = tid + i * 128;
            int row = task >> 4, seg = task & 15;
            cp16(sK + (uint32_t)(row * ATS + seg * 4) * 4,
                 k + (size_t)(kof + row) * HDD + seg * 4);
            cp16(sV + (uint32_t)(row * ATS + seg * 4) * 4,
                 v + (size_t)row * SS + kof + seg * 4);
        }
        cp_commit();
    };

    float l_i[2] = {0.f, 0.f};
    float O[8][4];
#pragma unroll
    for (int nf = 0; nf < 8; nf++)
#pragma unroll
        for (int r = 0; r < 4; r++) O[nf][r] = 0.f;

    const uint32_t aOff = (uint32_t)((w * 16 + (lane & 15)) * ATS) * 4 + (lane >> 4) * 16;
    const uint32_t bOff = (uint32_t)((((lane >> 4) & 1) * 8 + (lane & 7)) * ATS) * 4
                        + ((lane >> 3) & 1) * 16;
    const int shfl_s0 = (lane & ~3) | (tg >> 1);
    const int shfl_s1 = shfl_s0 | 2;
    const bool todd = tg & 1;

    const int ntiles = (vlen + 63) >> 6;

    for (int kt = 0; kt < ntiles; kt++) {
        stage_kv(kt);
        cp_wait<0>();
        __syncthreads();

        float sacc[8][4];
#pragma unroll
        for (int nf = 0; nf < 8; nf++)
#pragma unroll
            for (int r = 0; r < 4; r++) sacc[nf][r] = 0.f;

#pragma unroll
        for (int k8 = 0; k8 < 8; k8++) {
            const uint32_t kb = k8 * 32;
            uint32_t qh[4];
            ldsm4(qh[0], qh[1], qh[2], qh[3], sQh + aOff + kb);
#pragma unroll
            for (int bbq = 0; bbq < 4; bbq++) {
                uint32_t kh[4];
                ldsm4(kh[0], kh[1], kh[2], kh[3],
                      sK + bOff + (uint32_t)(bbq * 16 * ATS) * 4 + kb);
                mma_tf32(sacc[bbq*2+0], qh, &kh[0]);
                mma_tf32(sacc[bbq*2+1], qh, &kh[2]);
            }
        }

        // ---- p = exp(s/8) (masked -> 0); accumulate row sums; p back to sacc ----
        const int kbase = kt * 64;
#pragma unroll
        for (int nf = 0; nf < 8; nf++) {
            int cg = kbase + nf * 8 + 2 * tg;
            bool mk0 = cg >= vlen, mk1 = (cg + 1) >= vlen;
#pragma unroll
            for (int hh = 0; hh < 2; hh++) {
                float p0 = mk0 ? 0.f : fast_exp(sacc[nf][hh*2+0] * 0.125f);
                float p1 = mk1 ? 0.f : fast_exp(sacc[nf][hh*2+1] * 0.125f);
                l_i[hh] += p0 + p1;
                sacc[nf][hh*2+0] = tf32r(p0);
                sacc[nf][hh*2+1] = tf32r(p1);
            }
        }

        // ---- O += P V; P A-fragments via quad shuffles ----
#pragma unroll
        for (int k8 = 0; k8 < 8; k8++) {
            const uint32_t kb = k8 * 32;
            float e0 = sacc[k8][0], e1 = sacc[k8][1];
            float f0 = sacc[k8][2], f1 = sacc[k8][3];
            float e0a = __shfl_sync(0xffffffffu, e0, shfl_s0);
            float e1a = __shfl_sync(0xffffffffu, e1, shfl_s0);
            float f0a = __shfl_sync(0xffffffffu, f0, shfl_s0);
            float f1a = __shfl_sync(0xffffffffu, f1, shfl_s0);
            float e0b = __shfl_sync(0xffffffffu, e0, shfl_s1);
            float e1b = __shfl_sync(0xffffffffu, e1, shfl_s1);
            float f0b = __shfl_sync(0xffffffffu, f0, shfl_s1);
            float f1b = __shfl_sync(0xffffffffu, f1, shfl_s1);
            uint32_t ap[4];
            ap[0] = __float_as_uint(todd ? e1a : e0a);
            ap[1] = __float_as_uint(todd ? f1a : f0a);
            ap[2] = __float_as_uint(todd ? e1b : e0b);
            ap[3] = __float_as_uint(todd ? f1b : f0b);
#pragma unroll
            for (int bbv = 0; bbv < 4; bbv++) {
                uint32_t r0, r1, r2, r3;
                ldsm4(r0, r1, r2, r3, sV + bOff + (uint32_t)(bbv * 16 * ATS) * 4 + kb);
                uint32_t b0[2] = {r0, r1}, b1[2] = {r2, r3};
                mma_tf32(O[bbv*2+0], ap, b0);
                mma_tf32(O[bbv*2+1], ap, b1);
            }
        }
        __syncthreads();
    }

    // ---- epilogue: quad-reduce row sums, normalize, store rounded ----
#pragma unroll
    for (int hh = 0; hh < 2; hh++) {
        float ls = l_i[hh];
        ls += __shfl_xor_sync(0xffffffffu, ls, 1);
        ls += __shfl_xor_sync(0xffffffffu, ls, 2);
        float inv = 1.f / ls;
        int srow = qt * QROWS + w * 16 + grp + hh * 8;
#pragma unroll
        for (int nf = 0; nf < 8; nf++) {
            int hd = nf * 8 + 2 * tg;
            float2 val = make_float2(tf32r(O[nf][hh*2+0] * inv), tf32r(O[nf][hh*2+1] * inv));
            *(float2*)&out[((size_t)b * SS + srow) * DD + h * HDD + hd] = val;
        }
    }
}

// ---------------------------------------------------------------------------
extern "C" void kernel_launch(void* const* d_in, const int* in_sizes, int n_in,
                              void* d_out, int out_size) {
    (void)in_sizes; (void)n_in; (void)out_size;
    const float* queries    = (const float*)d_in[0];
    const float* keys       = (const float*)d_in[1];
    const float* values     = (const float*)d_in[2];
    const int*   valid_lens = (const int*)  d_in[3];
    const float* Wq         = (const float*)d_in[4];
    const float* Wk         = (const float*)d_in[5];
    const float* Wv         = (const float*)d_in[6];
    const float* Wo         = (const float*)d_in[7];
    float* out = (float*)d_out;

    float *pq, *pk, *pv, *pa, *pwt, *pat;
    cudaGetSymbolAddress((void**)&pq, g_q);
    cudaGetSymbolAddress((void**)&pk, g_k);
    cudaGetSymbolAddress((void**)&pv, g_v);
    cudaGetSymbolAddress((void**)&pa, g_attn);
    cudaGetSymbolAddress((void**)&pwt, g_wt);
    cudaGetSymbolAddress((void**)&pat, g_at);

    const int gemm_smem = 4 * 128 * STR2 * sizeof(float);     // 73728
    cudaFuncSetAttribute(gemm32<true>,  cudaFuncAttributeMaxDynamicSharedMemorySize, gemm_smem);
    cudaFuncSetAttribute(gemm32<false>, cudaFuncAttributeMaxDynamicSharedMemorySize, gemm_smem);
    const int attn_smem = 3 * KTILE * sizeof(float);          // 52224 -> 4 CTAs/SM
    cudaFuncSetAttribute(attn_mma, cudaFuncAttributeMaxDynamicSharedMemorySize, attn_smem);

    // prep
    dim3 pw_grid(32, 32, 4), pw_blk(32, 32);
    prep_w<<<pw_grid, pw_blk>>>(Wq, Wk, Wv, Wo, pwt);
    dim3 pa_grid(M_TOT * GKP / 4 / 256, 1, 3);
    prep_a<<<pa_grid, 256>>>((const float4*)queries, (const float4*)keys,
                             (const float4*)values, (float4*)pat);

    // fused QKV projections (256 thr, 2 CTAs/SM — R14 config)
    dim3 gq(DD / 128, M_TOT / 128, 3);
    gemm32<true><<<gq, 256, gemm_smem>>>(pat, pwt, pq, pk, pv);

    // attention
    dim3 agrid(SS / QROWS, BB * HH);
    attn_mma<<<agrid, 128, attn_smem>>>(valid_lens, pa);

    // output projection
    dim3 go(DD / 128, M_TOT / 128, 1);
    gemm32<false><<<go, 256, gemm_smem>>>(pa, pwt + (size_t)3 * DD * DD, out, nullptr, nullptr);
}

// round 17
// speedup vs baseline: 1.0601x; 1.0381x over previous
#include <cuda_runtime.h>
#include <math.h>
#include <stdint.h>

#define BB 4
#define SS 2048
#define DD 1024
#define HH 16
#define HDD 64
#define M_TOT (BB*SS)     // 8192
#define GKP 1024
#define BK2 32
#define NCH2 (GKP/BK2)    // 32
#define STR2 36           // f32 per smem row (144B)
#define ATS 68
#define QROWS 64
#define KTILE (64*ATS)

// ---------------------------------------------------------------------------
__device__ float g_q[(size_t)BB*HH*SS*HDD];
__device__ float g_k[(size_t)BB*HH*SS*HDD];       // [bh][s][hd], tf32-rounded
__device__ float g_v[(size_t)BB*HH*SS*HDD];       // [bh][hd][s], tf32-rounded (transposed)
__device__ float g_attn[(size_t)BB*SS*DD];
__device__ float g_wt[(size_t)4*DD*DD];
__device__ float g_at[(size_t)3*M_TOT*GKP];

// ---------------------------------------------------------------------------
__device__ __forceinline__ uint32_t smem_u32(const void* p) {
    return (uint32_t)__cvta_generic_to_shared(p);
}
__device__ __forceinline__ void cp16(uint32_t dst, const void* src) {
    asm volatile("cp.async.cg.shared.global [%0], [%1], 16;" :: "r"(dst), "l"(src));
}
__device__ __forceinline__ void cp_commit() {
    asm volatile("cp.async.commit_group;" ::: "memory");
}
template<int N>
__device__ __forceinline__ void cp_wait() {
    asm volatile("cp.async.wait_group %0;" :: "n"(N) : "memory");
}
__device__ __forceinline__ void ldsm4(uint32_t& r0, uint32_t& r1, uint32_t& r2, uint32_t& r3,
                                      uint32_t addr) {
    asm volatile("ldmatrix.sync.aligned.m8n8.x4.shared.b16 {%0,%1,%2,%3}, [%4];"
                 : "=r"(r0), "=r"(r1), "=r"(r2), "=r"(r3) : "r"(addr));
}
__device__ __forceinline__ uint32_t to_tf32(uint32_t x) {
    uint32_t y;
    asm("cvt.rna.tf32.f32 %0, %1;" : "=r"(y) : "r"(x));
    return y;
}
__device__ __forceinline__ float tf32r(float x) {
    return __uint_as_float(to_tf32(__float_as_uint(x)));
}
__device__ __forceinline__ void mma_tf32(float* c, const uint32_t* a, const uint32_t* b) {
    asm volatile("mma.sync.aligned.m16n8k8.row.col.f32.tf32.tf32.f32 "
                 "{%0,%1,%2,%3}, {%4,%5,%6,%7}, {%8,%9}, {%0,%1,%2,%3};"
                 : "+f"(c[0]), "+f"(c[1]), "+f"(c[2]), "+f"(c[3])
                 : "r"(a[0]), "r"(a[1]), "r"(a[2]), "r"(a[3]), "r"(b[0]), "r"(b[1]));
}

// ---------------------------------------------------------------------------
__global__ void __launch_bounds__(1024) prep_w(const float* __restrict__ W0,
                                               const float* __restrict__ W1,
                                               const float* __restrict__ W2,
                                               const float* __restrict__ W3,
                                               float* __restrict__ WT) {
    __shared__ float t[32][33];
    const float* W = (blockIdx.z == 0) ? W0 : (blockIdx.z == 1) ? W1
                   : (blockIdx.z == 2) ? W2 : W3;
    float* out = WT + (size_t)blockIdx.z * DD * DD;
    int k0 = blockIdx.y * 32, n0 = blockIdx.x * 32;
    t[threadIdx.y][threadIdx.x] = W[(size_t)(k0 + threadIdx.y) * 1024 + n0 + threadIdx.x];
    __syncthreads();
    out[(size_t)(n0 + threadIdx.y) * 1024 + k0 + threadIdx.x] = tf32r(t[threadIdx.x][threadIdx.y]);
}

__global__ void __launch_bounds__(256) prep_a(const float4* __restrict__ A0,
                                              const float4* __restrict__ A1,
                                              const float4* __restrict__ A2,
                                              float4* __restrict__ out) {
    const float4* A = (blockIdx.z == 0) ? A0 : (blockIdx.z == 1) ? A1 : A2;
    int idx = blockIdx.x * 256 + threadIdx.x;
    float4 v = A[idx];
    v.x = tf32r(v.x); v.y = tf32r(v.y); v.z = tf32r(v.z); v.w = tf32r(v.w);
    out[(size_t)blockIdx.z * (M_TOT * GKP / 4) + idx] = v;
}

// ---------------------------------------------------------------------------
// tf32 GEMM (R14 config): CTA 128x128, 8 warps (2m x 4n), warp tile 64x32,
// BK=32, 256 threads, 2 CTAs/SM.
// ---------------------------------------------------------------------------
template<bool QKV>
__global__ void __launch_bounds__(256, 2) gemm32(const float* __restrict__ Abase,
                                                 const float* __restrict__ Bbase,
                                                 float* __restrict__ Cq,
                                                 float* __restrict__ Ck,
                                                 float* __restrict__ Cv) {
    extern __shared__ float smg[];
    const uint32_t sbase = smem_u32(smg);

    const int z    = QKV ? blockIdx.z : 0;
    const int tid  = threadIdx.x;
    const int lane = tid & 31;
    const int warp = tid >> 5;
    const int wm   = warp & 1;
    const int wn   = warp >> 1;
    const int m0   = blockIdx.y * 128;
    const int n0   = blockIdx.x * 128;

    const float* A = Abase + (QKV ? (size_t)z * M_TOT * GKP : 0);
    const float* B = Bbase + (QKV ? (size_t)z * DD * DD : 0);
    const float* Arow = A + (size_t)m0 * GKP;
    const float* Brow = B + (size_t)n0 * GKP;

    auto load_chunk = [&](int buf, int c) {
        const size_t kof = (size_t)c * BK2;
        const uint32_t dA = sbase + (buf ? 4608u : 0u) * 4u;
        const uint32_t dB = sbase + (buf ? 13824u : 9216u) * 4u;
#pragma unroll
        for (int u = 0; u < 4; u++) {
            int task = tid + u * 256;
            int row  = task >> 3;
            int seg  = task & 7;
            uint32_t so = (uint32_t)(row * STR2 + seg * 4) * 4;
            cp16(dA + so, Arow + (size_t)row * GKP + kof + seg * 4);
            cp16(dB + so, Brow + (size_t)row * GKP + kof + seg * 4);
        }
        cp_commit();
    };

    float acc[4][4][4];
#pragma unroll
    for (int i = 0; i < 4; i++)
#pragma unroll
        for (int j = 0; j < 4; j++)
#pragma unroll
            for (int r = 0; r < 4; r++) acc[i][j][r] = 0.f;

    load_chunk(0, 0);

    for (int c = 0; c < NCH2; c++) {
        const int buf = c & 1;
        if (c + 1 < NCH2) {
            load_chunk(buf ^ 1, c + 1);
            cp_wait<1>();
        } else {
            cp_wait<0>();
        }
        __syncthreads();

        const uint32_t sA = sbase + (buf ? 4608u : 0u) * 4u;
        const uint32_t sB = sbase + (buf ? 13824u : 9216u) * 4u;
        const uint32_t aBase = sA + (uint32_t)((wm * 64 + (lane & 15)) * STR2) * 4
                             + (lane >> 4) * 16;
        const uint32_t bBase = sB + (uint32_t)((wn * 32 + ((lane >> 4) & 1) * 8 + (lane & 7)) * STR2) * 4
                             + ((lane >> 3) & 1) * 16;
#pragma unroll
        for (int k8 = 0; k8 < 4; k8++) {
            const uint32_t kb = k8 * 32;
            uint32_t a[4][4];
#pragma unroll
            for (int mf = 0; mf < 4; mf++)
                ldsm4(a[mf][0], a[mf][1], a[mf][2], a[mf][3],
                      aBase + (uint32_t)(mf * 16 * STR2) * 4 + kb);
            uint32_t b[4][2];
#pragma unroll
            for (int bb = 0; bb < 2; bb++) {
                uint32_t r0, r1, r2, r3;
                ldsm4(r0, r1, r2, r3, bBase + (uint32_t)(bb * 16 * STR2) * 4 + kb);
                b[bb * 2 + 0][0] = r0; b[bb * 2 + 0][1] = r1;
                b[bb * 2 + 1][0] = r2; b[bb * 2 + 1][1] = r3;
            }
#pragma unroll
            for (int mf = 0; mf < 4; mf++)
#pragma unroll
                for (int nf = 0; nf < 4; nf++)
                    mma_tf32(acc[mf][nf], a[mf], b[nf]);
        }
        __syncthreads();
    }

    const int grp = lane >> 2;
    const int tg  = lane & 3;
#pragma unroll
    for (int mf = 0; mf < 4; mf++) {
#pragma unroll
        for (int nf = 0; nf < 4; nf++) {
            int n = n0 + wn * 32 + nf * 8 + tg * 2;
#pragma unroll
            for (int half = 0; half < 2; half++) {
                int m = m0 + wm * 64 + mf * 16 + grp + half * 8;
                float2 v = make_float2(acc[mf][nf][half * 2], acc[mf][nf][half * 2 + 1]);
                if (!QKV) {
                    *(float2*)&Cq[(size_t)m * DD + n] = v;
                } else {
                    int b_ = m >> 11, s_ = m & 2047;
                    int h_ = n >> 6,  hd = n & 63;
                    if (z == 0) {
                        *(float2*)&Cq[((size_t)(b_ * HH + h_) * SS + s_) * HDD + hd] = v;
                    } else if (z == 1) {
                        v.x = tf32r(v.x); v.y = tf32r(v.y);
                        *(float2*)&Ck[((size_t)(b_ * HH + h_) * SS + s_) * HDD + hd] = v;
                    } else {
                        size_t base = ((size_t)(b_ * HH + h_) * HDD + hd) * SS + s_;
                        Cv[base]      = tf32r(v.x);
                        Cv[base + SS] = tf32r(v.y);
                    }
                }
            }
        }
    }
}

// ---------------------------------------------------------------------------
__device__ __forceinline__ float fast_exp(float x) {
    float t = fmaxf(x * 1.4426950408889634f, -126.0f);
    int   i = __float2int_rn(t);
    float f = t - (float)i;
    float p = 1.3333558146428443e-3f;
    p = fmaf(p, f, 9.6181291076284771e-3f);
    p = fmaf(p, f, 5.5504108664821580e-2f);
    p = fmaf(p, f, 2.4022650695910072e-1f);
    p = fmaf(p, f, 6.9314718055994531e-1f);
    p = fmaf(p, f, 1.0f);
    return p * __int_as_float((i + 127) << 23);
}

// ---------------------------------------------------------------------------
// Flash attention v10: R14 math (online max, shuffle-P, 4 CTAs/SM) +
// split-group cp.async pipelining: K staged in its own commit group so
// K(t+1) staging overlaps softmax/PV(t) and V(t) staging overlaps S-mma(t).
// smem floats: Qh@0, K@KTILE, V@2*KTILE
// ---------------------------------------------------------------------------
__global__ void __launch_bounds__(128, 4) attn_mma(const int* __restrict__ valid_lens,
                                                   float* __restrict__ out) {
    extern __shared__ float smf[];
    float* Qh = smf;

    int vl[4];
#pragma unroll
    for (int i = 0; i < 4; i++) vl[i] = valid_lens[i];
    int ord[4] = {0, 1, 2, 3};
#pragma unroll
    for (int i = 0; i < 3; i++)
#pragma unroll
        for (int j = i + 1; j < 4; j++)
            if (vl[ord[j]] > vl[ord[i]]) { int t = ord[i]; ord[i] = ord[j]; ord[j] = t; }

    const int qt = blockIdx.x;
    const int b  = ord[blockIdx.y >> 4];
    const int h  = blockIdx.y & 15;
    const int vlen = vl[b];
    const int bh = b * HH + h;

    const float* q = g_q + (size_t)bh * (SS * HDD);
    const float* k = g_k + (size_t)bh * (SS * HDD);
    const float* v = g_v + (size_t)bh * (HDD * SS);

    const int tid  = threadIdx.x;
    const int lane = tid & 31;
    const int w    = tid >> 5;
    const int grp  = lane >> 2;
    const int tg   = lane & 3;

    const uint32_t sQh = smem_u32(Qh);
    const uint32_t sK  = sQh + (uint32_t)(KTILE) * 4u;
    const uint32_t sV  = sQh + (uint32_t)(2 * KTILE) * 4u;

#pragma unroll
    for (int i = 0; i < 8; i++) {
        int idx = tid + i * 128;
        int row = idx >> 4, c4 = (idx & 15) << 2;
        float4 t = *(const float4*)&q[(size_t)(qt * QROWS + row) * HDD + c4];
        t.x = tf32r(t.x); t.y = tf32r(t.y); t.z = tf32r(t.z); t.w = tf32r(t.w);
        *(float4*)&Qh[row * ATS + c4] = t;
    }

    auto stage_k = [&](int kt) {
        const int kof = kt * 64;
#pragma unroll
        for (int i = 0; i < 8; i++) {
            int task = tid + i * 128;
            int row = task >> 4, seg = task & 15;
            cp16(sK + (uint32_t)(row * ATS + seg * 4) * 4,
                 k + (size_t)(kof + row) * HDD + seg * 4);
        }
        cp_commit();
    };
    auto stage_v = [&](int kt) {
        const int kof = kt * 64;
#pragma unroll
        for (int i = 0; i < 8; i++) {
            int task = tid + i * 128;
            int row = task >> 4, seg = task & 15;
            cp16(sV + (uint32_t)(row * ATS + seg * 4) * 4,
                 v + (size_t)row * SS + kof + seg * 4);
        }
        cp_commit();
    };

    float m_i[2] = {-1e30f, -1e30f}, l_i[2] = {0.f, 0.f};
    float O[8][4];
#pragma unroll
    for (int nf = 0; nf < 8; nf++)
#pragma unroll
        for (int r = 0; r < 4; r++) O[nf][r] = 0.f;

    const uint32_t aOff = (uint32_t)((w * 16 + (lane & 15)) * ATS) * 4 + (lane >> 4) * 16;
    const uint32_t bOff = (uint32_t)((((lane >> 4) & 1) * 8 + (lane & 7)) * ATS) * 4
                        + ((lane >> 3) & 1) * 16;
    const int shfl_s0 = (lane & ~3) | (tg >> 1);
    const int shfl_s1 = shfl_s0 | 2;
    const bool todd = tg & 1;

    const int ntiles = (vlen + 63) >> 6;
    stage_k(0);          // group: K(0)
    stage_v(0);          // group: V(0)

    for (int kt = 0; kt < ntiles; kt++) {
        cp_wait<1>();    // K(kt) landed (V(kt) may still be in flight)
        __syncthreads();

        // ---- S = Qh K^T ----
        float sacc[8][4];
#pragma unroll
        for (int nf = 0; nf < 8; nf++)
#pragma unroll
            for (int r = 0; r < 4; r++) sacc[nf][r] = 0.f;

#pragma unroll
        for (int k8 = 0; k8 < 8; k8++) {
            const uint32_t kb = k8 * 32;
            uint32_t qh[4];
            ldsm4(qh[0], qh[1], qh[2], qh[3], sQh + aOff + kb);
#pragma unroll
            for (int bbq = 0; bbq < 4; bbq++) {
                uint32_t kh[4];
                ldsm4(kh[0], kh[1], kh[2], kh[3],
                      sK + bOff + (uint32_t)(bbq * 16 * ATS) * 4 + kb);
                mma_tf32(sacc[bbq*2+0], qh, &kh[0]);
                mma_tf32(sacc[bbq*2+1], qh, &kh[2]);
            }
        }
        __syncthreads();                 // K buffer free
        if (kt + 1 < ntiles) stage_k(kt + 1);   // overlaps softmax + PV

        // ---- scale + mask ----
        const int kbase = kt * 64;
#pragma unroll
        for (int nf = 0; nf < 8; nf++) {
            int cg = kbase + nf * 8 + 2 * tg;
            bool mk0 = cg >= vlen, mk1 = (cg + 1) >= vlen;
#pragma unroll
            for (int hh = 0; hh < 2; hh++) {
                sacc[nf][hh*2+0] = mk0 ? -1e30f : sacc[nf][hh*2+0] * 0.125f;
                sacc[nf][hh*2+1] = mk1 ? -1e30f : sacc[nf][hh*2+1] * 0.125f;
            }
        }

        // ---- online softmax; p (tf32-rounded) back into sacc ----
#pragma unroll
        for (int hh = 0; hh < 2; hh++) {
            float mx = -1e30f;
#pragma unroll
            for (int nf = 0; nf < 8; nf++)
                mx = fmaxf(mx, fmaxf(sacc[nf][hh*2], sacc[nf][hh*2+1]));
            mx = fmaxf(mx, __shfl_xor_sync(0xffffffffu, mx, 1));
            mx = fmaxf(mx, __shfl_xor_sync(0xffffffffu, mx, 2));
            float m_new = fmaxf(m_i[hh], mx);
            float scl = fast_exp(m_i[hh] - m_new);
            m_i[hh] = m_new;
            float ps = 0.f;
#pragma unroll
            for (int nf = 0; nf < 8; nf++) {
                float p0 = fast_exp(sacc[nf][hh*2+0] - m_new);
                float p1 = fast_exp(sacc[nf][hh*2+1] - m_new);
                ps += p0 + p1;
                sacc[nf][hh*2+0] = tf32r(p0);
                sacc[nf][hh*2+1] = tf32r(p1);
            }
            ps += __shfl_xor_sync(0xffffffffu, ps, 1);
            ps += __shfl_xor_sync(0xffffffffu, ps, 2);
            l_i[hh] = l_i[hh] * scl + ps;
#pragma unroll
            for (int nf = 0; nf < 8; nf++) {
                O[nf][hh*2+0] *= scl;
                O[nf][hh*2+1] *= scl;
            }
        }

        cp_wait<1>();    // V(kt) landed (K(kt+1) may still be in flight)
        __syncthreads();

        // ---- O += P V; P A-fragments via quad shuffles ----
#pragma unroll
        for (int k8 = 0; k8 < 8; k8++) {
            const uint32_t kb = k8 * 32;
            float e0 = sacc[k8][0], e1 = sacc[k8][1];
            float f0 = sacc[k8][2], f1 = sacc[k8][3];
            float e0a = __shfl_sync(0xffffffffu, e0, shfl_s0);
            float e1a = __shfl_sync(0xffffffffu, e1, shfl_s0);
            float f0a = __shfl_sync(0xffffffffu, f0, shfl_s0);
            float f1a = __shfl_sync(0xffffffffu, f1, shfl_s0);
            float e0b = __shfl_sync(0xffffffffu, e0, shfl_s1);
            float e1b = __shfl_sync(0xffffffffu, e1, shfl_s1);
            float f0b = __shfl_sync(0xffffffffu, f0, shfl_s1);
            float f1b = __shfl_sync(0xffffffffu, f1, shfl_s1);
            uint32_t ap[4];
            ap[0] = __float_as_uint(todd ? e1a : e0a);
            ap[1] = __float_as_uint(todd ? f1a : f0a);
            ap[2] = __float_as_uint(todd ? e1b : e0b);
            ap[3] = __float_as_uint(todd ? f1b : f0b);
#pragma unroll
            for (int bbv = 0; bbv < 4; bbv++) {
                uint32_t r0, r1, r2, r3;
                ldsm4(r0, r1, r2, r3, sV + bOff + (uint32_t)(bbv * 16 * ATS) * 4 + kb);
                uint32_t b0[2] = {r0, r1}, b1[2] = {r2, r3};
                mma_tf32(O[bbv*2+0], ap, b0);
                mma_tf32(O[bbv*2+1], ap, b1);
            }
        }
        __syncthreads();                 // V buffer free
        if (kt + 1 < ntiles) stage_v(kt + 1);   // overlaps next S-mma
    }

#pragma unroll
    for (int hh = 0; hh < 2; hh++) {
        float inv = 1.f / l_i[hh];
        int srow = qt * QROWS + w * 16 + grp + hh * 8;
#pragma unroll
        for (int nf = 0; nf < 8; nf++) {
            int hd = nf * 8 + 2 * tg;
            float2 val = make_float2(tf32r(O[nf][hh*2+0] * inv), tf32r(O[nf][hh*2+1] * inv));
            *(float2*)&out[((size_t)b * SS + srow) * DD + h * HDD + hd] = val;
        }
    }
}

// ---------------------------------------------------------------------------
extern "C" void kernel_launch(void* const* d_in, const int* in_sizes, int n_in,
                              void* d_out, int out_size) {
    (void)in_sizes; (void)n_in; (void)out_size;
    const float* queries    = (const float*)d_in[0];
    const float* keys       = (const float*)d_in[1];
    const float* values     = (const float*)d_in[2];
    const int*   valid_lens = (const int*)  d_in[3];
    const float* Wq         = (const float*)d_in[4];
    const float* Wk         = (const float*)d_in[5];
    const float* Wv         = (const float*)d_in[6];
    const float* Wo         = (const float*)d_in[7];
    float* out = (float*)d_out;

    float *pq, *pk, *pv, *pa, *pwt, *pat;
    cudaGetSymbolAddress((void**)&pq, g_q);
    cudaGetSymbolAddress((void**)&pk, g_k);
    cudaGetSymbolAddress((void**)&pv, g_v);
    cudaGetSymbolAddress((void**)&pa, g_attn);
    cudaGetSymbolAddress((void**)&pwt, g_wt);
    cudaGetSymbolAddress((void**)&pat, g_at);

    const int gemm_smem = 4 * 128 * STR2 * sizeof(float);     // 73728
    cudaFuncSetAttribute(gemm32<true>,  cudaFuncAttributeMaxDynamicSharedMemorySize, gemm_smem);
    cudaFuncSetAttribute(gemm32<false>, cudaFuncAttributeMaxDynamicSharedMemorySize, gemm_smem);
    const int attn_smem = 3 * KTILE * sizeof(float);          // 52224 -> 4 CTAs/SM
    cudaFuncSetAttribute(attn_mma, cudaFuncAttributeMaxDynamicSharedMemorySize, attn_smem);

    // prep
    dim3 pw_grid(32, 32, 4), pw_blk(32, 32);
    prep_w<<<pw_grid, pw_blk>>>(Wq, Wk, Wv, Wo, pwt);
    dim3 pa_grid(M_TOT * GKP / 4 / 256, 1, 3);
    prep_a<<<pa_grid, 256>>>((const float4*)queries, (const float4*)keys,
                             (const float4*)values, (float4*)pat);

    // fused QKV projections
    dim3 gq(DD / 128, M_TOT / 128, 3);
    gemm32<true><<<gq, 256, gemm_smem>>>(pat, pwt, pq, pk, pv);

    // attention
    dim3 agrid(SS / QROWS, BB * HH);
    attn_mma<<<agrid, 128, attn_smem>>>(valid_lens, pa);

    // output projection
    dim3 go(DD / 128, M_TOT / 128, 1);
    gemm32<false><<<go, 256, gemm_smem>>>(pa, pwt + (size_t)3 * DD * DD, out, nullptr, nullptr);
}